// round 14
// baseline (speedup 1.0000x reference)
#include <cuda_runtime.h>
#include <math.h>

#define NPTS 4096
#define KN   30
#define HID  32
#define GD   16
#define NCELL 256
#define CAP  64
#define TPB  512
#define WARPS 16
#define QPW  4
#define MAXNU 8
#define FULL 0xffffffffu
#define SENT 0xffffffffu
#define PI_F 3.14159265358979f
#define TWO_LOG2E 2.885390081777927f   // 2*log2(e)

__device__ float4 g_pb[MAXNU][NPTS];   // (px, py, id_bits, label)
__device__ int    g_cs[MAXNU][NCELL + 1];

// FROZEN reference rounding chain (validated bit-exact R7-R13):
//   pn = rn( rn(px*px) + rn(py*py) )
//   t  = fma(qy,py, rn(qx*px))
//   d2 = rn( rn(qn - 2t) + pn )
__device__ __forceinline__ float d2_ref(float qxx, float qyy, float qn,
                                        float px, float py) {
    float pn = __fadd_rn(__fmul_rn(px, px), __fmul_rn(py, py));
    float t  = __fmaf_rn(qyy, py, __fmul_rn(qxx, px));
    return __fadd_rn(__fsub_rn(qn, __fmul_rn(2.0f, t)), pn);
}

__device__ __forceinline__ unsigned fkey(float f) {   // injective, order-preserving
    unsigned u = __float_as_uint(f);
    return u ^ (unsigned)(((int)u >> 31) | 0x80000000);
}

__device__ __forceinline__ float ex2(float x) {
    float r; asm("ex2.approx.f32 %0, %1;" : "=f"(r) : "f"(x)); return r;
}
__device__ __forceinline__ float rcp(float x) {
    float r; asm("rcp.approx.f32 %0, %1;" : "=f"(r) : "f"(x)); return r;
}

// pair compare-exchange on 32-bit key (ties: both sides keep own -> multiset safe)
__device__ __forceinline__ void ceP(unsigned &k, unsigned &p, int j, bool asc, int lane) {
    unsigned pk = __shfl_xor_sync(FULL, k, j);
    unsigned pp = __shfl_xor_sync(FULL, p, j);
    bool up = (((lane & j) == 0) == asc);
    bool take = up ? (pk < k) : (pk > k);
    if (take) { k = pk; p = pp; }
}

// ---- kernel 1: bin points into 16x16 grid, once per sample ----
__global__ void __launch_bounds__(256) bin_kernel(
    const float* __restrict__ u,
    const float* __restrict__ ix, const float* __restrict__ iy)
{
    __shared__ int cnts[NCELL];
    __shared__ int wsum[8];
    const int s = blockIdx.x, tid = threadIdx.x;
    const int lane = tid & 31, w = tid >> 5;

    cnts[tid] = 0;
    __syncthreads();
    for (int i = tid; i < NPTS; i += 256) {
        float px = ix[s * NPTS + i], py = iy[s * NPTS + i];
        int cx = min(GD - 1, (int)(px * GD));
        int cy = min(GD - 1, (int)(py * GD));
        atomicAdd(&cnts[cy * GD + cx], 1);
    }
    __syncthreads();
    int v = cnts[tid];
    int inc = v;
#pragma unroll
    for (int o = 1; o < 32; o <<= 1) {
        int t = __shfl_up_sync(FULL, inc, o);
        if (lane >= o) inc += t;
    }
    if (lane == 31) wsum[w] = inc;
    __syncthreads();
    int base = 0;
    for (int k = 0; k < w; k++) base += wsum[k];
    int excl = base + inc - v;
    __syncthreads();
    cnts[tid] = excl;
    g_cs[s][tid] = excl;
    if (tid == 255) g_cs[s][NCELL] = excl + v;
    __syncthreads();
    for (int i = tid; i < NPTS; i += 256) {
        float px = ix[s * NPTS + i], py = iy[s * NPTS + i];
        int cx = min(GD - 1, (int)(px * GD));
        int cy = min(GD - 1, (int)(py * GD));
        int pos = atomicAdd(&cnts[cy * GD + cx], 1);
        g_pb[s][pos] = make_float4(px, py, __int_as_float(i), u[s * NPTS + i]);
    }
}

// ---- kernel 2: per-warp query KNN + MLP-softmax blend ----
__global__ void __launch_bounds__(TPB, 3) knn_main(
    const float* __restrict__ qx, const float* __restrict__ qy,
    const float* __restrict__ W1, const float* __restrict__ b1,
    const float* __restrict__ W2,
    float* __restrict__ out, int Q)
{
    extern __shared__ float4 sp[];                   // 64 KB (px,py,id,lab)
    __shared__ int cs[NCELL + 1];
    __shared__ unsigned kbuf[WARPS][CAP];            // 4 KB
    __shared__ unsigned pbuf[WARPS][CAP];            // 4 KB
    __shared__ float4 mlp[HID];                      // (c1x, c1y, cb, w2m)
    __shared__ float sW2sum;

    const int s    = blockIdx.y;
    const int tid  = threadIdx.x;
    const int lane = tid & 31;
    const int w    = tid >> 5;

    for (int i = tid; i < NPTS; i += TPB) sp[i] = g_pb[s][i];
    if (tid <= NCELL) cs[tid] = g_cs[s][tid];
    if (tid < HID) {
        mlp[tid] = make_float4(TWO_LOG2E * W1[tid],
                               TWO_LOG2E * W1[HID + tid],
                               TWO_LOG2E * b1[tid],
                               -2.0f * W2[tid]);
    }
    if (tid == 0) {
        float acc = 0.0f;
        for (int i = 0; i < HID; i++) acc += W2[i];
        sW2sum = acc;
    }
    __syncthreads();

    const int qbase = blockIdx.x * (WARPS * QPW) + w * QPW;
    for (int qi = 0; qi < QPW; qi++) {
        const int q = qbase + qi;
        const float qxx = qx[s * Q + q];
        const float qyy = qy[s * Q + q];
        const float qn  = __fadd_rn(__fmul_rn(qxx, qxx), __fmul_rn(qyy, qyy));

        // threshold radius: clipped-disk area targeting ~44 points
        const float A = 44.0f / 4096.0f;
        float r = 0.05851f;                          // sqrt(A/pi)
        const float mnx = fminf(qxx, 1.0f - qxx);
        const float mny = fminf(qyy, 1.0f - qyy);
        if (mnx < r || mny < r) {
#pragma unroll
            for (int it = 0; it < 2; it++) {
                float ax = fminf(mnx / r, 1.0f);
                float ay = fminf(mny / r, 1.0f);
                float fx = 1.0f - (acosf(ax) - ax * sqrtf(fmaxf(0.f, 1.f - ax * ax))) / PI_F;
                float fy = 1.0f - (acosf(ay) - ay * sqrtf(fmaxf(0.f, 1.f - ay * ay))) / PI_F;
                r = sqrtf(A / (PI_F * fx * fy));
            }
        }
        float T = r * r;

        int cnt = 0;
        for (int attempt = 0; attempt < 8; attempt++) {
            cnt = 0;
            const float rr = sqrtf(T) * 1.0002f;     // d2-rounding slack
            const int cx0 = max(0,      (int)floorf((qxx - rr) * GD));
            const int cx1 = min(GD - 1, (int)floorf((qxx + rr) * GD));
            const int cy0 = max(0,      (int)floorf((qyy - rr) * GD));
            const int cy1 = min(GD - 1, (int)floorf((qyy + rr) * GD));
            for (int cy = cy0; cy <= cy1; cy++) {
                const int b0  = cs[cy * GD + cx0];
                const int b1e = cs[cy * GD + cx1 + 1];
                for (int base = b0; base < b1e; base += 32) {
                    const int j = base + lane;
                    const bool act = (j < b1e);
                    float4 p = act ? sp[j] : make_float4(1e9f, 1e9f, 0.f, 0.f);
                    float dd = d2_ref(qxx, qyy, qn, p.x, p.y);
                    bool acc = act && (dd <= T);
                    unsigned m = __ballot_sync(FULL, acc);
                    if (acc) {
                        int off = cnt + __popc(m & ((1u << lane) - 1u));
                        if (off < CAP) {
                            kbuf[w][off] = fkey(dd);
                            pbuf[w][off] = (unsigned)j;
                        }
                    }
                    cnt += __popc(m);
                }
            }
            if (cnt >= KN && cnt <= CAP) break;
            T *= (cnt > CAP) ? (50.0f / (float)cnt)
                             : (45.0f / fmaxf((float)cnt, 8.0f));
        }

        // ---- smallest-32 of <=64 by 32-bit key (exact d2 order; ties repaired) ----
        const int n = min(cnt, CAP);
        unsigned k0 = (lane      < n) ? kbuf[w][lane]      : SENT;
        unsigned p0 = (lane      < n) ? pbuf[w][lane]      : 0u;
        unsigned k1 = (32 + lane < n) ? kbuf[w][32 + lane] : SENT;
        unsigned p1 = (32 + lane < n) ? pbuf[w][32 + lane] : 0u;
#pragma unroll
        for (int k = 2; k <= 16; k <<= 1) {
#pragma unroll
            for (int j = k >> 1; j > 0; j >>= 1) {
                bool asc = ((lane & k) == 0);
                ceP(k0, p0, j, asc, lane);
                ceP(k1, p1, j, asc, lane);
            }
        }
#pragma unroll
        for (int j = 16; j > 0; j >>= 1) { ceP(k0, p0, j, true, lane); ceP(k1, p1, j, false, lane); }
        if (k1 < k0) { k0 = k1; p0 = p1; }          // elementwise min -> bitonic 32-smallest
#pragma unroll
        for (int j = 16; j > 0; j >>= 1) ceP(k0, p0, j, true, lane);
        // lanes 0..31: 32 smallest keys ascending; selected set = lanes 0..29

        // ---- rare boundary-tie repair: enforce lax.top_k smallest-id-first ----
        {
            unsigned key29 = __shfl_sync(FULL, k0, 29);
            unsigned tiem  = __ballot_sync(FULL, k0 == key29);
            bool straddle  = ((tiem >> 30) != 0u) && (key29 != SENT);
            if (straddle) {
                bool intie = (tiem >> lane) & 1u;
                int myid = intie ? __float_as_int(sp[p0].z) : 0x7fffffff;
                int gbase = __ffs(tiem) - 1;
                int rank = 0;
                unsigned mm = tiem;
                while (mm) {
                    int l = __ffs(mm) - 1; mm &= mm - 1;
                    int lid = __shfl_sync(FULL, myid, l);
                    if (intie && (lid < myid || (lid == myid && l < lane))) rank++;
                }
                unsigned newp = p0;
                mm = tiem;
                while (mm) {
                    int l = __ffs(mm) - 1; mm &= mm - 1;
                    int lrank = __shfl_sync(FULL, rank, l);
                    unsigned lp = __shfl_sync(FULL, p0, l);
                    if (intie && (gbase + lrank) == lane) newp = lp;
                }
                p0 = newp;
            }
        }

        // ---- epilogue: logit = sumW2 - sum w2m_i * rcp(exp2(c.rel)+1) ----
        float logit = __int_as_float(0xff800000);
        float lab = 0.0f;
        if (lane < KN) {
            const float4 p = sp[p0];
            lab = p.w;
            const float rx = p.x - qxx;
            const float ry = p.y - qyy;
            float acc = 0.0f;
#pragma unroll
            for (int i = 0; i < HID; i++) {
                const float4 c = mlp[i];
                float t = ex2(fmaf(rx, c.x, fmaf(ry, c.y, c.z)));
                acc = fmaf(c.w, rcp(t + 1.0f), acc);
            }
            logit = acc + sW2sum;        // b2 cancels in softmax
        }
        float lmax = logit;
#pragma unroll
        for (int o = 16; o; o >>= 1) lmax = fmaxf(lmax, __shfl_xor_sync(FULL, lmax, o));
        const float wgt = (lane < KN) ? __expf(logit - lmax) : 0.0f;
        float ws = wgt, os = wgt * lab;
#pragma unroll
        for (int o = 16; o; o >>= 1) {
            ws += __shfl_xor_sync(FULL, ws, o);
            os += __shfl_xor_sync(FULL, os, o);
        }
        if (lane == 0) out[s * Q + q] = __fdividef(os, ws);
    }
}

extern "C" void kernel_launch(void* const* d_in, const int* in_sizes, int n_in,
                              void* d_out, int out_size) {
    const float* u  = (const float*)d_in[0];
    const float* ix = (const float*)d_in[1];
    const float* iy = (const float*)d_in[2];
    const float* x  = (const float*)d_in[3];
    const float* y  = (const float*)d_in[4];
    const float* W1 = (const float*)d_in[5];
    const float* b1 = (const float*)d_in[6];
    const float* W2 = (const float*)d_in[7];
    // d_in[8] = b2 : constant shift, cancels in softmax
    float* out = (float*)d_out;

    const int nu = in_sizes[0] / NPTS;   // 4
    const int Q  = in_sizes[3] / nu;     // 16384

    bin_kernel<<<nu, 256>>>(u, ix, iy);

    cudaFuncSetAttribute(knn_main,
                         cudaFuncAttributeMaxDynamicSharedMemorySize,
                         NPTS * (int)sizeof(float4));
    dim3 grid(Q / (WARPS * QPW), nu);    // (256, 4)
    knn_main<<<grid, TPB, NPTS * sizeof(float4)>>>(
        x, y, W1, b1, W2, out, Q);
}

// round 15
// speedup vs baseline: 1.0125x; 1.0125x over previous
#include <cuda_runtime.h>
#include <math.h>

#define NPTS 4096
#define KN   30
#define HID  32
#define GD   16
#define NCELL 256
#define CAP  64
#define TPB  512
#define WARPS 16
#define BLKX 111               // 111*4 = 444 = 148 SMs * 3 blocks -> ONE wave
#define MAXNU 8
#define FULL 0xffffffffu
#define MAXK 0xffffffffffffffffULL
#define PI_F 3.14159265358979f
#define TWO_LOG2E 2.885390081777927f   // 2*log2(e)

__device__ float4 g_pb[MAXNU][NPTS];   // (px, py, id_bits, label)
__device__ int    g_cs[MAXNU][NCELL + 1];

// FROZEN reference rounding chain (validated bit-exact R7-R14):
//   pn = rn( rn(px*px) + rn(py*py) )
//   t  = fma(qy,py, rn(qx*px))
//   d2 = rn( rn(qn - 2t) + pn )
__device__ __forceinline__ float d2_ref(float qxx, float qyy, float qn,
                                        float px, float py) {
    float pn = __fadd_rn(__fmul_rn(px, px), __fmul_rn(py, py));
    float t  = __fmaf_rn(qyy, py, __fmul_rn(qxx, px));
    return __fadd_rn(__fsub_rn(qn, __fmul_rn(2.0f, t)), pn);
}

__device__ __forceinline__ unsigned fkey(float f) {   // injective, order-preserving
    unsigned u = __float_as_uint(f);
    return u ^ (unsigned)(((int)u >> 31) | 0x80000000);
}

__device__ __forceinline__ float ex2(float x) {
    float r; asm("ex2.approx.f32 %0, %1;" : "=f"(r) : "f"(x)); return r;
}
__device__ __forceinline__ float rcp(float x) {
    float r; asm("rcp.approx.f32 %0, %1;" : "=f"(r) : "f"(x)); return r;
}

__device__ __forceinline__ void ceX(unsigned long long &v, int j, bool asc, int lane) {
    unsigned long long pv = __shfl_xor_sync(FULL, v, j);
    bool keepmin = (((lane & j) == 0) == asc);
    unsigned long long mn = v < pv ? v : pv;
    unsigned long long mx = v < pv ? pv : v;
    v = keepmin ? mn : mx;
}

// ---- kernel 1: bin points into 16x16 grid, once per sample ----
__global__ void __launch_bounds__(256) bin_kernel(
    const float* __restrict__ u,
    const float* __restrict__ ix, const float* __restrict__ iy)
{
    __shared__ int cnts[NCELL];
    __shared__ int wsum[8];
    const int s = blockIdx.x, tid = threadIdx.x;
    const int lane = tid & 31, w = tid >> 5;

    cnts[tid] = 0;
    __syncthreads();
    for (int i = tid; i < NPTS; i += 256) {
        float px = ix[s * NPTS + i], py = iy[s * NPTS + i];
        int cx = min(GD - 1, (int)(px * GD));
        int cy = min(GD - 1, (int)(py * GD));
        atomicAdd(&cnts[cy * GD + cx], 1);
    }
    __syncthreads();
    int v = cnts[tid];
    int inc = v;
#pragma unroll
    for (int o = 1; o < 32; o <<= 1) {
        int t = __shfl_up_sync(FULL, inc, o);
        if (lane >= o) inc += t;
    }
    if (lane == 31) wsum[w] = inc;
    __syncthreads();
    int base = 0;
    for (int k = 0; k < w; k++) base += wsum[k];
    int excl = base + inc - v;
    __syncthreads();
    cnts[tid] = excl;
    g_cs[s][tid] = excl;
    if (tid == 255) g_cs[s][NCELL] = excl + v;
    __syncthreads();
    for (int i = tid; i < NPTS; i += 256) {
        float px = ix[s * NPTS + i], py = iy[s * NPTS + i];
        int cx = min(GD - 1, (int)(px * GD));
        int cy = min(GD - 1, (int)(py * GD));
        int pos = atomicAdd(&cnts[cy * GD + cx], 1);
        g_pb[s][pos] = make_float4(px, py, __int_as_float(i), u[s * NPTS + i]);
    }
}

// ---- kernel 2: per-warp query KNN + MLP-softmax blend ----
__global__ void __launch_bounds__(TPB, 3) knn_main(
    const float* __restrict__ qx, const float* __restrict__ qy,
    const float* __restrict__ W1, const float* __restrict__ b1,
    const float* __restrict__ W2,
    float* __restrict__ out, int Q)
{
    extern __shared__ float4 sp[];                   // 64 KB (px,py,id,lab)
    __shared__ int cs[NCELL + 1];
    __shared__ unsigned long long buf[WARPS][CAP];   // 8 KB
    __shared__ float4 mlp[HID];                      // (c1x, c1y, cb, w2m)
    __shared__ float sW2sum;

    const int s    = blockIdx.y;
    const int tid  = threadIdx.x;
    const int lane = tid & 31;
    const int w    = tid >> 5;

    for (int i = tid; i < NPTS; i += TPB) sp[i] = g_pb[s][i];
    if (tid <= NCELL) cs[tid] = g_cs[s][tid];
    if (tid < HID) {
        mlp[tid] = make_float4(TWO_LOG2E * W1[tid],
                               TWO_LOG2E * W1[HID + tid],
                               TWO_LOG2E * b1[tid],
                               -2.0f * W2[tid]);
    }
    if (tid == 0) {
        float acc = 0.0f;
        for (int i = 0; i < HID; i++) acc += W2[i];
        sW2sum = acc;
    }
    __syncthreads();

    // per-warp grid-stride over queries: one wave of blocks, warp-level balance
    for (int q = blockIdx.x * WARPS + w; q < Q; q += BLKX * WARPS) {
        const float qxx = qx[s * Q + q];
        const float qyy = qy[s * Q + q];
        const float qn  = __fadd_rn(__fmul_rn(qxx, qxx), __fmul_rn(qyy, qyy));

        // threshold radius: clipped-disk area targeting ~44 points
        const float A = 44.0f / 4096.0f;
        float r = 0.05851f;                          // sqrt(A/pi)
        const float mnx = fminf(qxx, 1.0f - qxx);
        const float mny = fminf(qyy, 1.0f - qyy);
        if (mnx < r || mny < r) {
#pragma unroll
            for (int it = 0; it < 2; it++) {
                float ax = fminf(mnx / r, 1.0f);
                float ay = fminf(mny / r, 1.0f);
                float fx = 1.0f - (acosf(ax) - ax * sqrtf(fmaxf(0.f, 1.f - ax * ax))) / PI_F;
                float fy = 1.0f - (acosf(ay) - ay * sqrtf(fmaxf(0.f, 1.f - ay * ay))) / PI_F;
                r = sqrtf(A / (PI_F * fx * fy));
            }
        }
        float T = r * r;

        int cnt = 0;
        for (int attempt = 0; attempt < 8; attempt++) {
            cnt = 0;
            const float rr = sqrtf(T) * 1.0002f;     // d2-rounding slack
            const int cx0 = max(0,      (int)floorf((qxx - rr) * GD));
            const int cx1 = min(GD - 1, (int)floorf((qxx + rr) * GD));
            const int cy0 = max(0,      (int)floorf((qyy - rr) * GD));
            const int cy1 = min(GD - 1, (int)floorf((qyy + rr) * GD));
            for (int cy = cy0; cy <= cy1; cy++) {
                const int b0  = cs[cy * GD + cx0];
                const int b1e = cs[cy * GD + cx1 + 1];
                for (int base = b0; base < b1e; base += 32) {
                    const int j = base + lane;
                    const bool act = (j < b1e);
                    float4 p = act ? sp[j] : make_float4(1e9f, 1e9f, 0.f, 0.f);
                    float dd = d2_ref(qxx, qyy, qn, p.x, p.y);
                    bool acc = act && (dd <= T);
                    unsigned m = __ballot_sync(FULL, acc);
                    if (acc) {
                        int off = cnt + __popc(m & ((1u << lane) - 1u));
                        if (off < CAP) {
                            unsigned id = (unsigned)__float_as_int(p.z);
                            buf[w][off] = ((unsigned long long)fkey(dd) << 24)
                                        | ((unsigned long long)id << 12)
                                        | (unsigned long long)j;
                        }
                    }
                    cnt += __popc(m);
                }
            }
            if (cnt >= KN && cnt <= CAP) break;
            T *= (cnt > CAP) ? (50.0f / (float)cnt)
                             : (45.0f / fmaxf((float)cnt, 8.0f));
        }

        // ---- exact smallest-32 selection (sorted) from <=64 keys ----
        const int n = min(cnt, CAP);
        unsigned long long v0 = (lane      < n) ? buf[w][lane]      : MAXK;
        unsigned long long v1 = (32 + lane < n) ? buf[w][32 + lane] : MAXK;
#pragma unroll
        for (int k = 2; k <= 16; k <<= 1) {
#pragma unroll
            for (int j = k >> 1; j > 0; j >>= 1) {
                bool asc = ((lane & k) == 0);
                ceX(v0, j, asc, lane);
                ceX(v1, j, asc, lane);
            }
        }
#pragma unroll
        for (int j = 16; j > 0; j >>= 1) { ceX(v0, j, true, lane); ceX(v1, j, false, lane); }
        v0 = (v0 < v1) ? v0 : v1;
#pragma unroll
        for (int j = 16; j > 0; j >>= 1) ceX(v0, j, true, lane);
        // lanes 0..29 hold exact lex top-30 (d2, id) ascending

        // ---- epilogue: logit = sumW2 - sum w2m_i * rcp(exp2(c.rel)+1) ----
        float logit = __int_as_float(0xff800000);
        float lab = 0.0f;
        if (lane < KN) {
            const int pos = (int)(v0 & 0xFFFULL);
            const float4 p = sp[pos];
            lab = p.w;
            const float rx = p.x - qxx;
            const float ry = p.y - qyy;
            float acc = 0.0f;
#pragma unroll
            for (int i = 0; i < HID; i++) {
                const float4 c = mlp[i];
                float t = ex2(fmaf(rx, c.x, fmaf(ry, c.y, c.z)));
                acc = fmaf(c.w, rcp(t + 1.0f), acc);
            }
            logit = acc + sW2sum;        // b2 cancels in softmax
        }
        float lmax = logit;
#pragma unroll
        for (int o = 16; o; o >>= 1) lmax = fmaxf(lmax, __shfl_xor_sync(FULL, lmax, o));
        const float wgt = (lane < KN) ? __expf(logit - lmax) : 0.0f;
        float ws = wgt, os = wgt * lab;
#pragma unroll
        for (int o = 16; o; o >>= 1) {
            ws += __shfl_xor_sync(FULL, ws, o);
            os += __shfl_xor_sync(FULL, os, o);
        }
        if (lane == 0) out[s * Q + q] = __fdividef(os, ws);
    }
}

extern "C" void kernel_launch(void* const* d_in, const int* in_sizes, int n_in,
                              void* d_out, int out_size) {
    const float* u  = (const float*)d_in[0];
    const float* ix = (const float*)d_in[1];
    const float* iy = (const float*)d_in[2];
    const float* x  = (const float*)d_in[3];
    const float* y  = (const float*)d_in[4];
    const float* W1 = (const float*)d_in[5];
    const float* b1 = (const float*)d_in[6];
    const float* W2 = (const float*)d_in[7];
    // d_in[8] = b2 : constant shift, cancels in softmax
    float* out = (float*)d_out;

    const int nu = in_sizes[0] / NPTS;   // 4
    const int Q  = in_sizes[3] / nu;     // 16384

    bin_kernel<<<nu, 256>>>(u, ix, iy);

    cudaFuncSetAttribute(knn_main,
                         cudaFuncAttributeMaxDynamicSharedMemorySize,
                         NPTS * (int)sizeof(float4));
    dim3 grid(BLKX, nu);                 // 444 blocks = one full wave
    knn_main<<<grid, TPB, NPTS * sizeof(float4)>>>(
        x, y, W1, b1, W2, out, Q);
}

// round 16
// speedup vs baseline: 1.4525x; 1.4346x over previous
#include <cuda_runtime.h>
#include <math.h>

#define NPTS 4096
#define KN   30
#define HID  32
#define GD   16
#define NCELL 256
#define CAP  64
#define TPB  512
#define WARPS 16
#define QPW  4
#define MAXNU 8
#define FULL 0xffffffffu
#define MAXK 0xffffffffffffffffULL
#define PI_F 3.14159265358979f

__device__ float4 g_pb[MAXNU][NPTS];   // (px, py, id_bits, label)
__device__ int    g_cs[MAXNU][NCELL + 1];

// FROZEN reference rounding chain (validated bit-exact R7-R15):
//   pn = rn( rn(px*px) + rn(py*py) )
//   t  = fma(qy,py, rn(qx*px))
//   d2 = rn( rn(qn - 2t) + pn )
__device__ __forceinline__ float d2_ref(float qxx, float qyy, float qn,
                                        float px, float py) {
    float pn = __fadd_rn(__fmul_rn(px, px), __fmul_rn(py, py));
    float t  = __fmaf_rn(qyy, py, __fmul_rn(qxx, px));
    return __fadd_rn(__fsub_rn(qn, __fmul_rn(2.0f, t)), pn);
}

__device__ __forceinline__ unsigned fkey(float f) {   // injective, order-preserving
    unsigned u = __float_as_uint(f);
    return u ^ (unsigned)(((int)u >> 31) | 0x80000000);
}

// ---- packed f32x2 helpers ----
__device__ __forceinline__ unsigned long long pack2(float lo, float hi) {
    unsigned long long r; asm("mov.b64 %0, {%1, %2};" : "=l"(r) : "f"(lo), "f"(hi)); return r;
}
__device__ __forceinline__ void unpack2(unsigned long long v, float &lo, float &hi) {
    asm("mov.b64 {%0, %1}, %2;" : "=f"(lo), "=f"(hi) : "l"(v));
}
__device__ __forceinline__ unsigned long long fma2(unsigned long long a,
                                                   unsigned long long b,
                                                   unsigned long long c) {
    unsigned long long d;
    asm("fma.rn.f32x2 %0, %1, %2, %3;" : "=l"(d) : "l"(a), "l"(b), "l"(c));
    return d;
}
__device__ __forceinline__ unsigned long long mul2(unsigned long long a,
                                                   unsigned long long b) {
    unsigned long long d;
    asm("mul.rn.f32x2 %0, %1, %2;" : "=l"(d) : "l"(a), "l"(b));
    return d;
}

// key-only bitonic compare-exchange (cheap: 1 shfl + minmax + sel)
__device__ __forceinline__ void ceK(unsigned &k, int j, bool asc, int lane) {
    unsigned pk = __shfl_xor_sync(FULL, k, j);
    bool up = (((lane & j) == 0) == asc);
    unsigned mn = min(k, pk), mx = max(k, pk);
    k = up ? mn : mx;
}

// ---- kernel 1: bin points into 16x16 grid, once per sample ----
__global__ void __launch_bounds__(256) bin_kernel(
    const float* __restrict__ u,
    const float* __restrict__ ix, const float* __restrict__ iy)
{
    __shared__ int cnts[NCELL];
    __shared__ int wsum[8];
    const int s = blockIdx.x, tid = threadIdx.x;
    const int lane = tid & 31, w = tid >> 5;

    cnts[tid] = 0;
    __syncthreads();
    for (int i = tid; i < NPTS; i += 256) {
        float px = ix[s * NPTS + i], py = iy[s * NPTS + i];
        int cx = min(GD - 1, (int)(px * GD));
        int cy = min(GD - 1, (int)(py * GD));
        atomicAdd(&cnts[cy * GD + cx], 1);
    }
    __syncthreads();
    int v = cnts[tid];
    int inc = v;
#pragma unroll
    for (int o = 1; o < 32; o <<= 1) {
        int t = __shfl_up_sync(FULL, inc, o);
        if (lane >= o) inc += t;
    }
    if (lane == 31) wsum[w] = inc;
    __syncthreads();
    int base = 0;
    for (int k = 0; k < w; k++) base += wsum[k];
    int excl = base + inc - v;
    __syncthreads();
    cnts[tid] = excl;
    g_cs[s][tid] = excl;
    if (tid == 255) g_cs[s][NCELL] = excl + v;
    __syncthreads();
    for (int i = tid; i < NPTS; i += 256) {
        float px = ix[s * NPTS + i], py = iy[s * NPTS + i];
        int cx = min(GD - 1, (int)(px * GD));
        int cy = min(GD - 1, (int)(py * GD));
        int pos = atomicAdd(&cnts[cy * GD + cx], 1);
        g_pb[s][pos] = make_float4(px, py, __int_as_float(i), u[s * NPTS + i]);
    }
}

// ---- kernel 2: per-warp query KNN + MLP-softmax blend ----
__global__ void __launch_bounds__(TPB, 3) knn_main(
    const float* __restrict__ qx, const float* __restrict__ qy,
    const float* __restrict__ W1, const float* __restrict__ b1,
    const float* __restrict__ W2,
    float* __restrict__ out, int Q)
{
    extern __shared__ float4 sp[];                   // 64 KB (px,py,id,lab)
    __shared__ int cs[NCELL + 1];
    __shared__ unsigned long long buf[WARPS][CAP];   // 8 KB (aliased post-sort)
    __shared__ ulonglong2 mA[HID / 2];               // (cx01, cy01) packed pairs
    __shared__ ulonglong2 mB[HID / 2];               // (cb01, w201) packed pairs

    const int s    = blockIdx.y;
    const int tid  = threadIdx.x;
    const int lane = tid & 31;
    const int w    = tid >> 5;
    const unsigned lml = (1u << lane) - 1u;

    for (int i = tid; i < NPTS; i += TPB) sp[i] = g_pb[s][i];
    if (tid <= NCELL) cs[tid] = g_cs[s][tid];
    if (tid < HID / 2) {
        ulonglong2 a, b;
        a.x = pack2(W1[2 * tid],       W1[2 * tid + 1]);        // W1 row x
        a.y = pack2(W1[HID + 2 * tid], W1[HID + 2 * tid + 1]);  // W1 row y
        b.x = pack2(b1[2 * tid],       b1[2 * tid + 1]);
        b.y = pack2(W2[2 * tid],       W2[2 * tid + 1]);
        mA[tid] = a;
        mB[tid] = b;
    }
    __syncthreads();

    // packed odd-tanh poly constants (tanh(x) ~ x(1 + x2(C3 + x2(C5 + x2*C7))))
    const unsigned long long C3  = pack2(-0.33333334f, -0.33333334f);
    const unsigned long long C5  = pack2( 0.13333334f,  0.13333334f);
    const unsigned long long C7  = pack2(-0.05396825f, -0.05396825f);
    const unsigned long long ONE = pack2(1.0f, 1.0f);

    const int qbase = blockIdx.x * (WARPS * QPW) + w * QPW;
    for (int qi = 0; qi < QPW; qi++) {
        const int q = qbase + qi;
        const float qxx = qx[s * Q + q];
        const float qyy = qy[s * Q + q];
        const float qn  = __fadd_rn(__fmul_rn(qxx, qxx), __fmul_rn(qyy, qyy));

        // threshold radius: clipped-disk area targeting ~44 points
        const float A = 44.0f / 4096.0f;
        float r = 0.05851f;                          // sqrt(A/pi)
        const float mnx = fminf(qxx, 1.0f - qxx);
        const float mny = fminf(qyy, 1.0f - qyy);
        if (mnx < r || mny < r) {
#pragma unroll
            for (int it = 0; it < 2; it++) {
                float ax = fminf(mnx / r, 1.0f);
                float ay = fminf(mny / r, 1.0f);
                float fx = 1.0f - (acosf(ax) - ax * sqrtf(fmaxf(0.f, 1.f - ax * ax))) / PI_F;
                float fy = 1.0f - (acosf(ay) - ay * sqrtf(fmaxf(0.f, 1.f - ay * ay))) / PI_F;
                r = sqrtf(A / (PI_F * fx * fy));
            }
        }
        float T = r * r;

        int cnt = 0;
        for (int attempt = 0; attempt < 8; attempt++) {
            cnt = 0;
            const float rr = sqrtf(T) * 1.0002f;     // d2-rounding slack
            const int cx0 = max(0,      (int)floorf((qxx - rr) * GD));
            const int cx1 = min(GD - 1, (int)floorf((qxx + rr) * GD));
            const int cy0 = max(0,      (int)floorf((qyy - rr) * GD));
            const int cy1 = min(GD - 1, (int)floorf((qyy + rr) * GD));
            for (int cy = cy0; cy <= cy1; cy++) {
                const int b0  = cs[cy * GD + cx0];
                const int b1e = cs[cy * GD + cx1 + 1];
                for (int base = b0; base < b1e; base += 32) {
                    const int j = base + lane;
                    const bool act = (j < b1e);
                    float4 p = act ? sp[j] : make_float4(1e9f, 1e9f, 0.f, 0.f);
                    float dd = d2_ref(qxx, qyy, qn, p.x, p.y);
                    bool acc = act && (dd <= T);
                    unsigned m = __ballot_sync(FULL, acc);
                    if (acc) {
                        int off = cnt + __popc(m & lml);
                        if (off < CAP) {
                            unsigned id = (unsigned)__float_as_int(p.z);
                            buf[w][off] = ((unsigned long long)fkey(dd) << 24)
                                        | ((unsigned long long)id << 12)
                                        | (unsigned long long)j;
                        }
                    }
                    cnt += __popc(m);
                }
            }
            if (cnt >= KN && cnt <= CAP) break;
            T *= (cnt > CAP) ? (50.0f / (float)cnt)
                             : (45.0f / fmaxf((float)cnt, 8.0f));
        }

        // ---- load payloads; key-only partial sort to find the 30th key ----
        const int n = min(cnt, CAP);
        const unsigned long long w0 = (lane      < n) ? buf[w][lane]      : MAXK;
        const unsigned long long w1 = (32 + lane < n) ? buf[w][32 + lane] : MAXK;
        const unsigned k0 = (unsigned)(w0 >> 24);    // fkey (sentinel 0xFFFFFFFF)
        const unsigned k1 = (unsigned)(w1 >> 24);
        unsigned a0 = k0, a1 = k1;
#pragma unroll
        for (int k = 2; k <= 16; k <<= 1) {
#pragma unroll
            for (int j = k >> 1; j > 0; j >>= 1) {
                bool asc = ((lane & k) == 0);
                ceK(a0, j, asc, lane);
                ceK(a1, j, asc, lane);
            }
        }
#pragma unroll
        for (int j = 16; j > 0; j >>= 1) { ceK(a0, j, true, lane); ceK(a1, j, false, lane); }
        unsigned mn32 = min(a0, a1);                 // 32 smallest (bitonic)
#pragma unroll
        for (int j = 16; j > 0; j >>= 1) ceK(mn32, j, true, lane);
        const unsigned k30 = __shfl_sync(FULL, mn32, KN - 1);   // 30th smallest key

        // ---- exact membership: key < k30, ties by smallest id (lax.top_k) ----
        bool in0 = (k0 < k30), in1 = (k1 < k30);
        const bool eq0 = (k0 == k30), eq1 = (k1 == k30);
        const unsigned meq0 = __ballot_sync(FULL, eq0);
        const unsigned meq1 = __ballot_sync(FULL, eq1);
        const int c_lt = __popc(__ballot_sync(FULL, in0)) + __popc(__ballot_sync(FULL, in1));
        const int need = KN - c_lt;                  // >= 1
        const int neq  = __popc(meq0) + __popc(meq1);
        unsigned* cbuf = reinterpret_cast<unsigned*>(&buf[w][0]);  // buf dead now
        if (neq == need) {                           // common case
            in0 |= eq0; in1 |= eq1;
        } else {                                     // rare (~1.5e-3): tie straddle
            if (eq0) cbuf[32 + __popc(meq0 & lml)] =
                ((unsigned)((w0 >> 12) & 0xFFFULL) << 6) | lane;
            if (eq1) cbuf[32 + __popc(meq0) + __popc(meq1 & lml)] =
                ((unsigned)((w1 >> 12) & 0xFFFULL) << 6) | 32u | lane;
            __syncwarp();
            if (lane == 0) {
                int m = min(neq, 32);
                unsigned used = 0;
                for (int t = 0; t < need && t < m; t++) {
                    unsigned best = 0xFFFFFFFFu; int bi = 0;
                    for (int e = 0; e < m; e++)
                        if (!((used >> e) & 1u) && cbuf[32 + e] < best) { best = cbuf[32 + e]; bi = e; }
                    used |= 1u << bi;
                }
                cbuf[100] = used;
            }
            __syncwarp();
            const unsigned used = cbuf[100];
            if (eq0) in0 |= (used >> (__popc(meq0 & lml))) & 1u;
            if (eq1) in1 |= (used >> (__popc(meq0) + __popc(meq1 & lml))) & 1u;
        }

        // ---- compact the 30 winners' (id,pos) into lanes 0..29 ----
        const unsigned m0 = __ballot_sync(FULL, in0);
        const unsigned m1 = __ballot_sync(FULL, in1);
        if (in0) cbuf[__popc(m0 & lml)]              = (unsigned)(w0 & 0xFFFFFFULL);
        if (in1) cbuf[__popc(m0) + __popc(m1 & lml)] = (unsigned)(w1 & 0xFFFFFFULL);
        __syncwarp();

        // ---- epilogue: packed-poly tanh MLP + softmax (no max shift) ----
        float logit = 0.0f, lab = 0.0f;
        if (lane < KN) {
            const unsigned ent = cbuf[lane];
            const float4 p = sp[ent & 0xFFFu];
            lab = p.w;
            const unsigned long long rxp = pack2(p.x - qxx, p.x - qxx);
            const unsigned long long ryp = pack2(p.y - qyy, p.y - qyy);
            unsigned long long acc = 0ULL;           // (0.f, 0.f)
#pragma unroll
            for (int i = 0; i < HID / 2; i++) {
                const ulonglong2 a = mA[i];
                const ulonglong2 b = mB[i];
                unsigned long long x  = fma2(rxp, a.x, fma2(ryp, a.y, b.x));
                unsigned long long x2 = mul2(x, x);
                unsigned long long g  = fma2(x2, C7, C5);
                g = fma2(x2, g, C3);
                g = fma2(x2, g, ONE);
                acc = fma2(mul2(x, g), b.y, acc);
            }
            float aLo, aHi; unpack2(acc, aLo, aHi);
            logit = aLo + aHi;                       // b2 cancels in softmax
        }
        const float wgt = (lane < KN) ? __expf(logit) : 0.0f;
        float ws = wgt, os = wgt * lab;
#pragma unroll
        for (int o = 16; o; o >>= 1) {
            ws += __shfl_xor_sync(FULL, ws, o);
            os += __shfl_xor_sync(FULL, os, o);
        }
        if (lane == 0) out[s * Q + q] = __fdividef(os, ws);
    }
}

extern "C" void kernel_launch(void* const* d_in, const int* in_sizes, int n_in,
                              void* d_out, int out_size) {
    const float* u  = (const float*)d_in[0];
    const float* ix = (const float*)d_in[1];
    const float* iy = (const float*)d_in[2];
    const float* x  = (const float*)d_in[3];
    const float* y  = (const float*)d_in[4];
    const float* W1 = (const float*)d_in[5];
    const float* b1 = (const float*)d_in[6];
    const float* W2 = (const float*)d_in[7];
    // d_in[8] = b2 : constant shift, cancels in softmax
    float* out = (float*)d_out;

    const int nu = in_sizes[0] / NPTS;   // 4
    const int Q  = in_sizes[3] / nu;     // 16384

    bin_kernel<<<nu, 256>>>(u, ix, iy);

    cudaFuncSetAttribute(knn_main,
                         cudaFuncAttributeMaxDynamicSharedMemorySize,
                         NPTS * (int)sizeof(float4));
    dim3 grid(Q / (WARPS * QPW), nu);    // (256, 4)
    knn_main<<<grid, TPB, NPTS * sizeof(float4)>>>(
        x, y, W1, b1, W2, out, Q);
}